// round 4
// baseline (speedup 1.0000x reference)
#include <cuda_runtime.h>
#include <cstdint>

// Problem constants
#define BATCH      256
#define TREES      64
#define FEAT       16080      // 120*134
#define MASK_W     1000
#define K_TOP      200
#define ROW_F4     (FEAT / 4)       // 4020
#define LIVE_F4    (MASK_W / 4)     // 250  (columns [0,1000) hold all nonzeros)
#define TAIL_F4    (ROW_F4 - LIVE_F4)  // 3770 zero float4s per row
#define NROWS      (BATCH * TREES)     // 16384 rv rows
#define NROWS_ALL  (NROWS + TREES)     // + 64 attention rows = 16448

// ---------------------------------------------------------------------------
// Kernel A: fused zero-fill + topk.
//   grid = (16, 16448), block = 256.
//   x in [0,15): zero-fill float4 columns [250, 4020) of row y
//                (rows 0..16383 = return_value rows; 16384..16447 = attention
//                 rows — contiguous in d_out, so one uniform base pointer).
//   x == 15:     y < 64 -> exact top-200 for tree y (binary-search threshold
//                selection, jax lower-index tie-break) + write
//                attention[y, 0:1000). y >= 64 -> exit.
//   The 64 topk blocks (~5us of block time) hide under the 0.99 GB store wave.
// ---------------------------------------------------------------------------
__global__ __launch_bounds__(256)
void zero_topk_kernel(const float* __restrict__ mask, float* __restrict__ out)
{
    const int tid = threadIdx.x;
    const int bx  = blockIdx.x;
    const int row = blockIdx.y;

    if (bx < 15) {
        // ---- zero-fill path: columns [LIVE_F4, ROW_F4) of this row ----
        const int c4 = bx * 256 + tid;            // 0 .. 3839
        if (c4 < TAIL_F4) {
            float4 z; z.x = 0.f; z.y = 0.f; z.z = 0.f; z.w = 0.f;
            float4* dst = reinterpret_cast<float4*>(out + (size_t)row * FEAT)
                          + (LIVE_F4 + c4);
            *dst = z;
        }
        return;
    }

    // ---- topk path: bx == 15 ----
    if (row >= TREES) return;
    const int t = row;
    float* att_row = out + (size_t)(NROWS + t) * FEAT;

    __shared__ unsigned int skey[MASK_W];
    __shared__ float        sval[MASK_W];
    __shared__ int s_cnt, s_cgt, s_ceq;

    // Load + order-preserving float->uint transform
    for (int i = tid; i < MASK_W; i += 256) {
        const float v = mask[t * MASK_W + i];
        sval[i] = v;
        const int s = __float_as_int(v);
        skey[i] = (s < 0) ? ~(unsigned int)s : ((unsigned int)s | 0x80000000u);
    }
    __syncthreads();

    // Register-cache this thread's 4 keys (sentinel 0 never selected:
    // midpoints are >= 1 and keys of finite floats are > 0)
    unsigned int k[4];
    #pragma unroll
    for (int q = 0; q < 4; ++q) {
        const int i = tid + q * 256;
        k[q] = (i < MASK_W) ? skey[i] : 0u;
    }

    // Binary search: thr = max T with count(key >= T) >= K_TOP (200th largest)
    unsigned int lo = 0u, hi = 0xFFFFFFFFu;
    while (lo < hi) {
        const unsigned int mid = lo + ((hi - lo) >> 1) + 1u;
        int c = 0;
        #pragma unroll
        for (int q = 0; q < 4; ++q) c += (k[q] >= mid);
        if (tid == 0) s_cnt = 0;
        __syncthreads();
        c = __reduce_add_sync(0xFFFFFFFFu, c);
        if ((tid & 31) == 0) atomicAdd(&s_cnt, c);
        __syncthreads();
        const int total = s_cnt;
        __syncthreads();
        if (total >= K_TOP) lo = mid; else hi = mid - 1u;
    }
    const unsigned int thr = lo;

    // Counts of strictly-greater and equal
    if (tid == 0) { s_cgt = 0; s_ceq = 0; }
    __syncthreads();
    int cg = 0, ce = 0;
    #pragma unroll
    for (int q = 0; q < 4; ++q) { cg += (k[q] > thr); ce += (k[q] == thr); }
    cg = __reduce_add_sync(0xFFFFFFFFu, cg);
    ce = __reduce_add_sync(0xFFFFFFFFu, ce);
    if ((tid & 31) == 0) { atomicAdd(&s_cgt, cg); atomicAdd(&s_ceq, ce); }
    __syncthreads();
    const int need  = K_TOP - s_cgt;   // equals to accept
    const int eqtot = s_ceq;

    // Write attention[t, 0:1000)
    #pragma unroll
    for (int q = 0; q < 4; ++q) {
        const int i = tid + q * 256;
        if (i < MASK_W) {
            bool sel = (k[q] > thr);
            if (k[q] == thr) {
                if (need >= eqtot) {
                    sel = true;                 // all ties fit (common case)
                } else {                        // boundary tie: lowest index wins
                    int r = 0;
                    for (int j = 0; j < i; ++j) r += (skey[j] == thr);
                    sel = (r < need);
                }
            }
            const float v = sval[i];
            att_row[i] = sel ? (1.0f / (1.0f + expf(-v))) : 0.0f;
        }
    }
}

// ---------------------------------------------------------------------------
// Kernel B: live region multiply.
//   One block per (b,t) row; threads 0..249 each write one float4 of
//   return_value[b,t, 0:1000) = x[b, 0:1000) * attention[t, 0:1000).
//   65.5 MB of stores; x (1 MB) and att (256 KB) are L2-resident.
// ---------------------------------------------------------------------------
__global__ __launch_bounds__(256)
void live_kernel(const float* __restrict__ x,
                 const float* __restrict__ att,
                 float*       __restrict__ out)
{
    const int c4  = threadIdx.x;
    if (c4 >= LIVE_F4) return;
    const int row = blockIdx.x;                 // b*TREES + t
    const int t   = row & (TREES - 1);
    const int b   = row >> 6;

    const float4 xa = reinterpret_cast<const float4*>(x   + (size_t)b * FEAT)[c4];
    const float4 aa = reinterpret_cast<const float4*>(att + (size_t)t * FEAT)[c4];
    float4 r;
    r.x = xa.x * aa.x;
    r.y = xa.y * aa.y;
    r.z = xa.z * aa.z;
    r.w = xa.w * aa.w;
    reinterpret_cast<float4*>(out + (size_t)row * FEAT)[c4] = r;
}

// ---------------------------------------------------------------------------
// Launch
// ---------------------------------------------------------------------------
extern "C" void kernel_launch(void* const* d_in, const int* in_sizes, int n_in,
                              void* d_out, int out_size)
{
    const float* x    = (const float*)d_in[0];   // (256, 120, 134) fp32
    const float* mask = (const float*)d_in[1];   // (64, 1000) fp32

    float* out = (float*)d_out;
    float* rv_out  = out;                                   // (256, 64, 16080)
    float* att_out = out + (size_t)NROWS * FEAT;            // (64, 16080)

    // A) zero-fill all row tails (rv rows + attention rows) with topk fused in
    dim3 gridA(16, NROWS_ALL);
    zero_topk_kernel<<<gridA, 256>>>(mask, out);

    // B) live multiply for columns [0, 1000)
    live_kernel<<<NROWS, 256>>>(x, att_out, rv_out);
}

// round 5
// speedup vs baseline: 1.0167x; 1.0167x over previous
#include <cuda_runtime.h>
#include <cstdint>

// Problem constants
#define BATCH      256
#define TREES      64
#define FEAT       16080        // 120*134
#define MASK_W     1000
#define K_TOP      200
#define ROW_F4     (FEAT / 4)   // 4020
#define LIVE_F4    (MASK_W / 4) // 250  (columns [0,1000) hold all nonzeros)
#define NROWS      (BATCH * TREES)   // 16384 rv rows
#define NROWS_ALL  (NROWS + TREES)   // + 64 attention rows

// ---------------------------------------------------------------------------
// Kernel A: warp-per-tree exact top-200, fully register-resident.
//   grid = 8 blocks x 256 threads = 64 warps; warp w handles tree w.
//   Each lane holds 32 keys (i = q*32 + lane) in registers. Binary-search the
//   order-preserving uint32 key domain for the 200th-largest key using only
//   __reduce_add_sync (no smem, no __syncthreads). Select key > thr plus
//   lowest-index equals (exact jax tie-break via ballot prefix on the rare
//   warp-uniform boundary-tie path). Writes attention[t, 0:1000) only.
// ---------------------------------------------------------------------------
__global__ __launch_bounds__(256)
void topk_kernel(const float* __restrict__ mask, float* __restrict__ att_out)
{
    const int warp = threadIdx.x >> 5;
    const int lane = threadIdx.x & 31;
    const int t    = blockIdx.x * 8 + warp;
    const unsigned FULL = 0xFFFFFFFFu;

    const float* mrow = mask + t * MASK_W;
    float*       arow = att_out + (size_t)t * FEAT;

    // Load 32 keys/lane; i = q*32 + lane (coalesced per q). Sentinel key 0 is
    // never counted: search midpoints are >= 1, and every finite float maps
    // to a key > 0 under the order-preserving transform.
    unsigned int k[32];
    float        v[32];
    #pragma unroll
    for (int q = 0; q < 32; ++q) {
        const int i = q * 32 + lane;
        if (i < MASK_W) {
            const float f = mrow[i];
            v[q] = f;
            const int s = __float_as_int(f);
            k[q] = (s < 0) ? ~(unsigned int)s : ((unsigned int)s | 0x80000000u);
        } else {
            v[q] = 0.0f;
            k[q] = 0u;
        }
    }

    // Binary search: thr = max T with count(key >= T) >= K_TOP (200th largest)
    unsigned int lo = 0u, hi = 0xFFFFFFFFu;
    while (lo < hi) {
        const unsigned int mid = lo + ((hi - lo) >> 1) + 1u;   // upper mid
        int c = 0;
        #pragma unroll
        for (int q = 0; q < 32; ++q) c += (k[q] >= mid);
        c = __reduce_add_sync(FULL, c);
        if (c >= K_TOP) lo = mid; else hi = mid - 1u;
    }
    const unsigned int thr = lo;

    // Strictly-greater and equal counts
    int cg = 0, ce = 0;
    #pragma unroll
    for (int q = 0; q < 32; ++q) { cg += (k[q] > thr); ce += (k[q] == thr); }
    cg = __reduce_add_sync(FULL, cg);
    ce = __reduce_add_sync(FULL, ce);
    const int need = K_TOP - cg;          // equals to accept (1 <= need <= ce)

    // Selection flags for equals
    bool sel_eq[32];
    if (need >= ce) {
        #pragma unroll
        for (int q = 0; q < 32; ++q) sel_eq[q] = true;    // all ties fit
    } else {
        // Boundary tie (warp-uniform branch): lowest indices win.
        // Index order is (q ascending, lane ascending) == i ascending.
        const unsigned lanemask_lt = (1u << lane) - 1u;
        int base = 0;
        #pragma unroll
        for (int q = 0; q < 32; ++q) {
            const unsigned m = __ballot_sync(FULL, k[q] == thr);
            sel_eq[q] = (base + __popc(m & lanemask_lt)) < need;
            base += __popc(m);
        }
    }

    // Write attention[t, 0:1000): selected -> sigmoid(v), else 0
    #pragma unroll
    for (int q = 0; q < 32; ++q) {
        const int i = q * 32 + lane;
        if (i < MASK_W) {
            const bool sel = (k[q] > thr) || (k[q] == thr && sel_eq[q]);
            arow[i] = sel ? (1.0f / (1.0f + expf(-v[q]))) : 0.0f;
        }
    }
}

// ---------------------------------------------------------------------------
// Kernel B: full-output store stream (the round-3 rv_kernel, extended).
//   grid = (16, 16448), block = 256; each thread stores one float4.
//   Rows [0, 16384): return_value rows — c4 < 250 multiplies x*att (both L2
//   resident), c4 >= 250 stores zeros. Rows [16384, 16448): attention rows —
//   zero only the tail (A already wrote columns [0,1000)).
//   ~1.056 GB of STG.128 in one contiguous DRAM-saturated stream.
// ---------------------------------------------------------------------------
__global__ __launch_bounds__(256)
void rv_kernel(const float* __restrict__ x,
               const float* __restrict__ att,
               float*       __restrict__ out)
{
    const int c4  = blockIdx.x * blockDim.x + threadIdx.x;   // float4 column
    if (c4 >= ROW_F4) return;
    const int row = blockIdx.y;

    if (row >= NROWS) {                    // attention row: zero tail only
        if (c4 >= LIVE_F4) {
            float4 z; z.x = 0.f; z.y = 0.f; z.z = 0.f; z.w = 0.f;
            reinterpret_cast<float4*>(out + (size_t)row * FEAT)[c4] = z;
        }
        return;
    }

    const int t = row & (TREES - 1);
    const int b = row >> 6;

    float4 r;
    if (c4 < LIVE_F4) {
        const float4 xa = reinterpret_cast<const float4*>(x   + (size_t)b * FEAT)[c4];
        const float4 aa = reinterpret_cast<const float4*>(att + (size_t)t * FEAT)[c4];
        r.x = xa.x * aa.x;
        r.y = xa.y * aa.y;
        r.z = xa.z * aa.z;
        r.w = xa.w * aa.w;
    } else {
        r.x = 0.0f; r.y = 0.0f; r.z = 0.0f; r.w = 0.0f;
    }
    reinterpret_cast<float4*>(out + (size_t)row * FEAT)[c4] = r;
}

// ---------------------------------------------------------------------------
// Launch
// ---------------------------------------------------------------------------
extern "C" void kernel_launch(void* const* d_in, const int* in_sizes, int n_in,
                              void* d_out, int out_size)
{
    const float* x    = (const float*)d_in[0];   // (256, 120, 134) fp32
    const float* mask = (const float*)d_in[1];   // (64, 1000) fp32

    float* out = (float*)d_out;
    float* att_out = out + (size_t)NROWS * FEAT; // (64, 16080) appended

    // A) warp-per-tree exact top-200 -> attention[t, 0:1000)
    topk_kernel<<<8, 256>>>(mask, att_out);

    // B) one contiguous store stream for the whole output
    dim3 gridB(16, NROWS_ALL);
    rv_kernel<<<gridB, 256>>>(x, att_out, out);
}